// round 3
// baseline (speedup 1.0000x reference)
#include <cuda_runtime.h>
#include <cuda_bf16.h>
#include <cstdint>

// Problem constants (match reference_code)
#define N0c 200000
#define N1c 50000
#define N2c 12500
#define N3c 3200
#define E0c 500000
#define E1c 125000
#define E2c 32000
#define DINc 128
#define DHc 256
#define DOUTc 128

// ---------------- scratch (static device globals; no allocations) ----------------
__device__ float g_mean[(size_t)N1c * DHc];   // mean aggregate buffer (reused per layer)
__device__ float g_h1[(size_t)N1c * DHc];     // layer-0 output (50000 x 256)
__device__ float g_h2[(size_t)N2c * DHc];     // layer-1 output (12500 x 256)
__device__ int   g_deg[N1c];
__device__ int   g_off[N1c + 1];
__device__ int   g_cur[N1c];
__device__ int   g_esrc[E0c];

// ---------------- CSR build ----------------
__global__ void zero_deg_kernel(int n) {
    int i = blockIdx.x * blockDim.x + threadIdx.x;
    if (i < n) g_deg[i] = 0;
}

__global__ void hist_kernel(const int* __restrict__ dst, int E) {
    int e = blockIdx.x * blockDim.x + threadIdx.x;
    if (e < E) atomicAdd(&g_deg[dst[e]], 1);
}

// One-pass chunked scan: 1024 threads, each owns a contiguous chunk.
// Two global passes, ONE block-scan round (vs 49 barrier rounds before).
__global__ void scan_kernel(int n, int E) {
    const int T = 1024;
    __shared__ int wsum[32];
    int tid = threadIdx.x, lane = tid & 31, wid = tid >> 5;
    int chunk = (n + T - 1) / T;
    int beg = min(tid * chunk, n), end = min(beg + chunk, n);

    int sum = 0;
    for (int i = beg; i < end; i++) sum += g_deg[i];

    // block-wide inclusive scan of per-thread sums
    int s = sum;
    #pragma unroll
    for (int o = 1; o < 32; o <<= 1) {
        int t = __shfl_up_sync(0xffffffffu, s, o);
        if (lane >= o) s += t;
    }
    if (lane == 31) wsum[wid] = s;
    __syncthreads();
    if (wid == 0) {
        int ws = wsum[lane];
        #pragma unroll
        for (int o = 1; o < 32; o <<= 1) {
            int t = __shfl_up_sync(0xffffffffu, ws, o);
            if (lane >= o) ws += t;
        }
        wsum[lane] = ws;
    }
    __syncthreads();
    int excl = s - sum + ((wid > 0) ? wsum[wid - 1] : 0);

    int run = excl;
    for (int i = beg; i < end; i++) {
        int d = g_deg[i];
        g_off[i] = run;
        g_cur[i] = run;
        run += d;
    }
    if (tid == 0) g_off[n] = E;
}

__global__ void bucket_kernel(const int* __restrict__ src, const int* __restrict__ dst, int E) {
    int e = blockIdx.x * blockDim.x + threadIdx.x;
    if (e < E) {
        int p = atomicAdd(&g_cur[dst[e]], 1);
        g_esrc[p] = src[e];
    }
}

// ---------------- aggregation: warp per target node, register accumulation ----------------
template <int D>
__global__ void aggregate_kernel(const float* __restrict__ X, float* __restrict__ mean, int n_tgt) {
    int w = (blockIdx.x * blockDim.x + threadIdx.x) >> 5;
    int lane = threadIdx.x & 31;
    if (w >= n_tgt) return;
    int beg = g_off[w], end = g_off[w + 1];
    float acc[D / 32];
    #pragma unroll
    for (int i = 0; i < D / 32; i++) acc[i] = 0.f;
    int e = beg;
    for (; e + 1 < end; e += 2) {   // 2-edge unroll for MLP
        int s0 = g_esrc[e], s1 = g_esrc[e + 1];
        const float4* r0 = (const float4*)(X + (size_t)s0 * D);
        const float4* r1 = (const float4*)(X + (size_t)s1 * D);
        #pragma unroll
        for (int i = 0; i < D / 128; i++) {
            float4 v0 = r0[lane + 32 * i];
            float4 v1 = r1[lane + 32 * i];
            acc[4 * i + 0] += v0.x + v1.x;
            acc[4 * i + 1] += v0.y + v1.y;
            acc[4 * i + 2] += v0.z + v1.z;
            acc[4 * i + 3] += v0.w + v1.w;
        }
    }
    if (e < end) {
        const float4* row = (const float4*)(X + (size_t)g_esrc[e] * D);
        #pragma unroll
        for (int i = 0; i < D / 128; i++) {
            float4 v = row[lane + 32 * i];
            acc[4 * i + 0] += v.x;
            acc[4 * i + 1] += v.y;
            acc[4 * i + 2] += v.z;
            acc[4 * i + 3] += v.w;
        }
    }
    float inv = 1.f / (float)max(end - beg, 1);
    float4* mrow = (float4*)(mean + (size_t)w * D);
    #pragma unroll
    for (int i = 0; i < D / 128; i++) {
        float4 o;
        o.x = acc[4 * i + 0] * inv;
        o.y = acc[4 * i + 1] * inv;
        o.z = acc[4 * i + 2] * inv;
        o.w = acc[4 * i + 3] * inv;
        mrow[lane + 32 * i] = o;
    }
}

// ---------------- tf32 tensor-core fused dual-A GEMM, cp.async double-buffered ----------------
// out = act( mean@Wl^T + Xtgt@Wr^T + b )
// Block tile 128x128, BK=32, 256 threads = 8 warps (2m x 4n), warp tile 64x32
// (4x4 m16n8k8 tf32 mma). Tiles staged in smem as raw fp32 via cp.async;
// tf32 conversion at fragment-read time.

__device__ __forceinline__ uint32_t f2tf32(float f) {
    uint32_t u;
    asm("cvt.rna.tf32.f32 %0, %1;" : "=r"(u) : "f"(f));
    return u;
}

__device__ __forceinline__ uint32_t smem_u32(const void* p) {
    return (uint32_t)__cvta_generic_to_shared(p);
}

__device__ __forceinline__ void cp16(uint32_t dst, const void* src, bool pred) {
    int sz = pred ? 16 : 0;
    asm volatile("cp.async.ca.shared.global [%0], [%1], 16, %2;\n"
                 :: "r"(dst), "l"(src), "r"(sz));
}

#define GEMM_BM 128
#define GEMM_BK 32
#define GEMM_LDS 36
#define GEMM_TILE_WORDS (GEMM_BM * GEMM_LDS)
#define GEMM_SMEM_BYTES (4 * GEMM_TILE_WORDS * 4)   // 2 bufs x (A + B) = 73728 B

__global__ void __launch_bounds__(256, 2) sage_gemm_tf32(
    const float* __restrict__ A0, const float* __restrict__ A1,
    const float* __restrict__ Wl, const float* __restrict__ Wr,
    const float* __restrict__ bias, float* __restrict__ out,
    int M, int N, int D, int relu)
{
    extern __shared__ float smem[];
    // layout: [buf0 A][buf0 B][buf1 A][buf1 B]
    float* tiles = smem;

    int tid = threadIdx.x;
    int lane = tid & 31, wid = tid >> 5;
    int wm = wid & 1;        // 0..1  -> 64-row half
    int wn = wid >> 1;       // 0..3  -> 32-col strip
    int g = lane >> 2, t = lane & 3;

    int rowBase = blockIdx.x * GEMM_BM, colBase = blockIdx.y * GEMM_BM;

    float acc[4][4][4];
    #pragma unroll
    for (int i = 0; i < 4; i++)
        #pragma unroll
        for (int j = 0; j < 4; j++)
            #pragma unroll
            for (int r = 0; r < 4; r++) acc[i][j][r] = 0.f;

    int ldr = tid >> 3;          // 0..31 (row within 32-row chunk)
    int ldc = (tid & 7) * 4;     // 0,4,...,28 (k offset)

    uint32_t smem_base = smem_u32(smem);
    const int NT = (2 * D) / GEMM_BK;

    auto load_tile = [&](int it, int buf) {
        int kt = it * GEMM_BK;
        const float* A = (kt < D) ? A0 : A1;
        const float* W = (kt < D) ? Wl : Wr;
        int kk = (kt < D) ? kt : (kt - D);
        uint32_t baseA = smem_base + (uint32_t)(buf * 2 * GEMM_TILE_WORDS) * 4;
        uint32_t baseB = baseA + (uint32_t)GEMM_TILE_WORDS * 4;
        #pragma unroll
        for (int s = 0; s < 4; s++) {
            int r = ldr + s * 32;
            int grow = rowBase + r;
            cp16(baseA + (uint32_t)(r * GEMM_LDS + ldc) * 4,
                 A + (size_t)grow * D + kk + ldc, grow < M);
            cp16(baseB + (uint32_t)(r * GEMM_LDS + ldc) * 4,
                 W + (size_t)(colBase + r) * D + kk + ldc, true);
        }
        asm volatile("cp.async.commit_group;\n");
    };

    load_tile(0, 0);
    asm volatile("cp.async.wait_group 0;\n");
    __syncthreads();

    for (int it = 0; it < NT; it++) {
        int cur = it & 1;
        if (it + 1 < NT) load_tile(it + 1, cur ^ 1);

        const float* Asf = tiles + cur * 2 * GEMM_TILE_WORDS;
        const float* Bsf = Asf + GEMM_TILE_WORDS;

        #pragma unroll
        for (int ks = 0; ks < GEMM_BK; ks += 8) {
            uint32_t af[4][4];
            #pragma unroll
            for (int mi = 0; mi < 4; mi++) {
                int m = wm * 64 + mi * 16;
                af[mi][0] = f2tf32(Asf[(m + g)     * GEMM_LDS + ks + t]);
                af[mi][1] = f2tf32(Asf[(m + g + 8) * GEMM_LDS + ks + t]);
                af[mi][2] = f2tf32(Asf[(m + g)     * GEMM_LDS + ks + t + 4]);
                af[mi][3] = f2tf32(Asf[(m + g + 8) * GEMM_LDS + ks + t + 4]);
            }
            uint32_t bf[4][2];
            #pragma unroll
            for (int ni = 0; ni < 4; ni++) {
                int n = wn * 32 + ni * 8;
                bf[ni][0] = f2tf32(Bsf[(n + g) * GEMM_LDS + ks + t]);
                bf[ni][1] = f2tf32(Bsf[(n + g) * GEMM_LDS + ks + t + 4]);
            }
            #pragma unroll
            for (int mi = 0; mi < 4; mi++)
                #pragma unroll
                for (int ni = 0; ni < 4; ni++) {
                    asm volatile(
                        "mma.sync.aligned.m16n8k8.row.col.f32.tf32.tf32.f32 "
                        "{%0,%1,%2,%3}, {%4,%5,%6,%7}, {%8,%9}, {%0,%1,%2,%3};"
                        : "+f"(acc[mi][ni][0]), "+f"(acc[mi][ni][1]),
                          "+f"(acc[mi][ni][2]), "+f"(acc[mi][ni][3])
                        : "r"(af[mi][0]), "r"(af[mi][1]), "r"(af[mi][2]), "r"(af[mi][3]),
                          "r"(bf[ni][0]), "r"(bf[ni][1]));
                }
        }

        if (it + 1 < NT)
            asm volatile("cp.async.wait_group 0;\n");
        __syncthreads();
    }

    // epilogue: bias + optional relu
    #pragma unroll
    for (int mi = 0; mi < 4; mi++) {
        #pragma unroll
        for (int ni = 0; ni < 4; ni++) {
            int col = colBase + wn * 32 + ni * 8 + t * 2;
            float b0v = bias[col], b1v = bias[col + 1];
            int row0 = rowBase + wm * 64 + mi * 16 + g;
            if (row0 < M) {
                float2 o;
                o.x = acc[mi][ni][0] + b0v;
                o.y = acc[mi][ni][1] + b1v;
                if (relu) { o.x = fmaxf(o.x, 0.f); o.y = fmaxf(o.y, 0.f); }
                *(float2*)(out + (size_t)row0 * N + col) = o;
            }
            int row1 = row0 + 8;
            if (row1 < M) {
                float2 o;
                o.x = acc[mi][ni][2] + b0v;
                o.y = acc[mi][ni][3] + b1v;
                if (relu) { o.x = fmaxf(o.x, 0.f); o.y = fmaxf(o.y, 0.f); }
                *(float2*)(out + (size_t)row1 * N + col) = o;
            }
        }
    }
}

// ---------------- host-side layer driver ----------------
static void run_layer(const float* X, const int* src, const int* dst,
                      int E, int n_tgt, int D,
                      const float* Wl, const float* Wr, const float* b,
                      float* outbuf, int Nout, int relu)
{
    zero_deg_kernel<<<(n_tgt + 255) / 256, 256>>>(n_tgt);
    hist_kernel<<<(E + 255) / 256, 256>>>(dst, E);
    scan_kernel<<<1, 1024>>>(n_tgt, E);
    bucket_kernel<<<(E + 255) / 256, 256>>>(src, dst, E);

    float* mean;
    cudaGetSymbolAddress((void**)&mean, g_mean);

    int aggBlocks = (n_tgt * 32 + 255) / 256;
    if (D == 128)
        aggregate_kernel<128><<<aggBlocks, 256>>>(X, mean, n_tgt);
    else
        aggregate_kernel<256><<<aggBlocks, 256>>>(X, mean, n_tgt);

    dim3 grid((n_tgt + 127) / 128, Nout / 128);
    sage_gemm_tf32<<<grid, 256, GEMM_SMEM_BYTES>>>(mean, X, Wl, Wr, b, outbuf, n_tgt, Nout, D, relu);
}

extern "C" void kernel_launch(void* const* d_in, const int* in_sizes, int n_in,
                              void* d_out, int out_size)
{
    const float* x    = (const float*)d_in[0];
    const int*   src0 = (const int*)d_in[1];
    const int*   dst0 = (const int*)d_in[2];
    const int*   src1 = (const int*)d_in[3];
    const int*   dst1 = (const int*)d_in[4];
    const int*   src2 = (const int*)d_in[5];
    const int*   dst2 = (const int*)d_in[6];
    const float* wl0  = (const float*)d_in[7];
    const float* wr0  = (const float*)d_in[8];
    const float* b0   = (const float*)d_in[9];
    const float* wl1  = (const float*)d_in[10];
    const float* wr1  = (const float*)d_in[11];
    const float* b1   = (const float*)d_in[12];
    const float* wl2  = (const float*)d_in[13];
    const float* wr2  = (const float*)d_in[14];
    const float* b2   = (const float*)d_in[15];
    float* out = (float*)d_out;

    cudaFuncSetAttribute(sage_gemm_tf32,
                         cudaFuncAttributeMaxDynamicSharedMemorySize, GEMM_SMEM_BYTES);

    float *h1, *h2;
    cudaGetSymbolAddress((void**)&h1, g_h1);
    cudaGetSymbolAddress((void**)&h2, g_h2);

    // Layer 0: x (N0 x 128) -> h1 (N1 x 256), relu
    run_layer(x,  src0, dst0, E0c, N1c, DINc, wl0, wr0, b0, h1, DHc, 1);
    // Layer 1: h1 (N1 x 256) -> h2 (N2 x 256), relu
    run_layer(h1, src1, dst1, E1c, N2c, DHc, wl1, wr1, b1, h2, DHc, 1);
    // Layer 2: h2 (N2 x 256) -> out (N3 x 128), no relu
    run_layer(h2, src2, dst2, E2c, N3c, DHc, wl2, wr2, b2, out, DOUTc, 0);
}